// round 5
// baseline (speedup 1.0000x reference)
#include <cuda_runtime.h>

namespace {
constexpr int S  = 8192;
constexpr int D  = 64;
constexpr int W  = 64;
constexpr int TQ = 32;            // queries per CTA
constexpr int KR = TQ + 2 * W;    // 160 key rows per CTA
constexpr int SP = 164;           // P row pitch (float4 aligned)
constexpr int NT = 256;           // 8 warps; each owns 4 query rows
constexpr int RWQ = 4;
// Ks (swizzled) [KR][64] + Qs [TQ][64] + Sc [TQ][SP]
constexpr int SMEM_FLOATS = KR * 64 + TQ * 64 + TQ * SP;
constexpr int SMEM_BYTES  = SMEM_FLOATS * 4;   // 70144 B -> 3 CTAs/SM (210KB<=228KB)
}

// ---- packed f32x2 helpers --------------------------------------------------
__device__ __forceinline__ unsigned long long ffma2(unsigned long long acc,
                                                    unsigned long long a,
                                                    unsigned long long b) {
    asm("fma.rn.f32x2 %0, %1, %2, %0;" : "+l"(acc) : "l"(a), "l"(b));
    return acc;
}
__device__ __forceinline__ unsigned long long dup2(float p) {
    unsigned long long u;
    asm("mov.b64 %0, {%1, %1};" : "=l"(u) : "f"(p));
    return u;
}
__device__ __forceinline__ float2 unpack2(unsigned long long u) {
    float2 v;
    asm("mov.b64 {%0, %1}, %2;" : "=f"(v.x), "=f"(v.y) : "l"(u));
    return v;
}

__global__ __launch_bounds__(NT, 3)
void swa_kernel(const float* __restrict__ Q,
                const float* __restrict__ K,
                const float* __restrict__ V,
                float* __restrict__ O) {
    extern __shared__ float sm[];
    float* Ks = sm;                 // KR x 64, float2-XOR-swizzled within row
    float* Qs = Ks + KR * 64;       // TQ x 64
    float* Sc = Qs + TQ * 64;       // TQ x SP  (normalized P, per-warp private)

    const int tile = blockIdx.x;
    const int b  = tile >> 8;
    const int qt = (tile & 255) * TQ;
    const int KB = qt - W;

    const float* kb = K + (size_t)b * S * D;
    const float* vb = V + (size_t)b * S * D;
    const float* qb = Q + (size_t)b * S * D;

    const int t = threadIdx.x;

    // ---------------- stage K (swizzled) and Q ----------------------------
    for (int idx = t; idx < KR * (D / 4); idx += NT) {
        int row = idx >> 4, c0 = idx & 15;
        int kg = KB + row;
        float4 k4 = make_float4(0.f, 0.f, 0.f, 0.f);
        if (kg >= 0 && kg < S)
            k4 = *(const float4*)(kb + (size_t)kg * D + 4 * c0);
        int x = row & 31;                       // pair (row,d2) -> 2*(d2^x)
        float* krow = Ks + row * 64;
        *(float2*)(krow + 2 * ((2 * c0)     ^ x)) = make_float2(k4.x, k4.y);
        *(float2*)(krow + 2 * ((2 * c0 + 1) ^ x)) = make_float2(k4.z, k4.w);
    }
    for (int idx = t; idx < TQ * (D / 4); idx += NT) {
        int row = idx >> 4, c = (idx & 15) << 2;
        *(float4*)(Qs + row * 64 + c) =
            *(const float4*)(qb + (size_t)(qt + row) * D + c);
    }
    __syncthreads();

    const int lane = t & 31;
    const int w    = t >> 5;   // warp w: rows [4w, 4w+4)

    float p[RWQ][5];           // scores -> normalized probs, register resident

    // ---------------- score GEMM, pass A: key cols s=0,1 ------------------
    {
        unsigned long long acc[RWQ][2];
        #pragma unroll
        for (int r = 0; r < RWQ; ++r) { acc[r][0] = 0ull; acc[r][1] = 0ull; }
        const float* k0 = Ks + lane * 64;
        const float* k1 = Ks + (lane + 32) * 64;

        #pragma unroll 2
        for (int d4 = 0; d4 < 16; ++d4) {
            ulonglong2 q2[RWQ];
            #pragma unroll
            for (int r = 0; r < RWQ; ++r)       // LDS.128 broadcast
                q2[r] = *(const ulonglong2*)(Qs + (RWQ * w + r) * 64 + 4 * d4);
            #pragma unroll
            for (int h = 0; h < 2; ++h) {
                int d2 = 2 * d4 + h;
                unsigned long long kk0 =
                    *(const unsigned long long*)(k0 + 2 * (d2 ^ lane));
                unsigned long long kk1 =
                    *(const unsigned long long*)(k1 + 2 * (d2 ^ lane));
                #pragma unroll
                for (int r = 0; r < RWQ; ++r) {
                    unsigned long long qq = h ? q2[r].y : q2[r].x;
                    acc[r][0] = ffma2(acc[r][0], qq, kk0);
                    acc[r][1] = ffma2(acc[r][1], qq, kk1);
                }
            }
        }
        #pragma unroll
        for (int r = 0; r < RWQ; ++r) {
            float2 v0 = unpack2(acc[r][0]);
            float2 v1 = unpack2(acc[r][1]);
            p[r][0] = (v0.x + v0.y) * 0.125f;
            p[r][1] = (v1.x + v1.y) * 0.125f;
        }
    }
    // ---------------- score GEMM, pass B: key cols s=2,3,4 ----------------
    {
        unsigned long long acc[RWQ][3];
        #pragma unroll
        for (int r = 0; r < RWQ; ++r)
            #pragma unroll
            for (int s = 0; s < 3; ++s) acc[r][s] = 0ull;
        const float* k2 = Ks + (lane + 64) * 64;
        const float* k3 = Ks + (lane + 96) * 64;
        const float* k4r = Ks + (lane + 128) * 64;

        #pragma unroll 2
        for (int d4 = 0; d4 < 16; ++d4) {
            ulonglong2 q2[RWQ];
            #pragma unroll
            for (int r = 0; r < RWQ; ++r)       // LDS.128 broadcast
                q2[r] = *(const ulonglong2*)(Qs + (RWQ * w + r) * 64 + 4 * d4);
            #pragma unroll
            for (int h = 0; h < 2; ++h) {
                int d2 = 2 * d4 + h;
                unsigned long long kk2 =
                    *(const unsigned long long*)(k2 + 2 * (d2 ^ lane));
                unsigned long long kk3 =
                    *(const unsigned long long*)(k3 + 2 * (d2 ^ lane));
                unsigned long long kk4 =
                    *(const unsigned long long*)(k4r + 2 * (d2 ^ lane));
                #pragma unroll
                for (int r = 0; r < RWQ; ++r) {
                    unsigned long long qq = h ? q2[r].y : q2[r].x;
                    acc[r][0] = ffma2(acc[r][0], qq, kk2);
                    acc[r][1] = ffma2(acc[r][1], qq, kk3);
                    acc[r][2] = ffma2(acc[r][2], qq, kk4);
                }
            }
        }
        #pragma unroll
        for (int r = 0; r < RWQ; ++r) {
            float2 v2 = unpack2(acc[r][0]);
            float2 v3 = unpack2(acc[r][1]);
            float2 v4 = unpack2(acc[r][2]);
            p[r][2] = (v2.x + v2.y) * 0.125f;
            p[r][3] = (v3.x + v3.y) * 0.125f;
            p[r][4] = (v4.x + v4.y) * 0.125f;
        }
    }

    // ---------------- in-register masked softmax (per warp-owned rows) ----
    #pragma unroll
    for (int r = 0; r < RWQ; ++r) {
        const int row = RWQ * w + r;
        const int lo = max(row, -KB);
        const int hi = min(row + 2 * W, S - 1 - KB);
        float m = -1e30f;
        #pragma unroll
        for (int s = 0; s < 5; ++s) {
            int j = lane + 32 * s;
            if (j >= lo && j <= hi) m = fmaxf(m, p[r][s]);
        }
        m = fmaxf(m, __shfl_xor_sync(0xffffffffu, m, 16));
        m = fmaxf(m, __shfl_xor_sync(0xffffffffu, m, 8));
        m = fmaxf(m, __shfl_xor_sync(0xffffffffu, m, 4));
        m = fmaxf(m, __shfl_xor_sync(0xffffffffu, m, 2));
        m = fmaxf(m, __shfl_xor_sync(0xffffffffu, m, 1));
        float ssum = 0.f;
        #pragma unroll
        for (int s = 0; s < 5; ++s) {
            int j = lane + 32 * s;
            float e = (j >= lo && j <= hi) ? __expf(p[r][s] - m) : 0.f;
            ssum += e;
            p[r][s] = e;
        }
        ssum += __shfl_xor_sync(0xffffffffu, ssum, 16);
        ssum += __shfl_xor_sync(0xffffffffu, ssum, 8);
        ssum += __shfl_xor_sync(0xffffffffu, ssum, 4);
        ssum += __shfl_xor_sync(0xffffffffu, ssum, 2);
        ssum += __shfl_xor_sync(0xffffffffu, ssum, 1);
        float rinv = 1.f / ssum;
        #pragma unroll
        for (int s = 0; s < 5; ++s)             // conflict-free scalar STS
            Sc[row * SP + lane + 32 * s] = p[r][s] * rinv;
    }
    __syncwarp();   // intra-warp transpose only: Sc rows [4w,4w+4) are private

    // ---------------- AV: V straight from gmem (coalesced, L1-reused) -----
    {
        unsigned long long a[RWQ] = {0ull, 0ull, 0ull, 0ull};
        const bool interior = (KB >= 0) && (KB + KR <= S);
        const float* vcol = vb + 2 * lane;

        if (interior) {
            #pragma unroll 2
            for (int j4 = 0; j4 < KR; j4 += 4) {
                float4 p4[RWQ];
                #pragma unroll
                for (int r = 0; r < RWQ; ++r)   // LDS.128 broadcast
                    p4[r] = *(const float4*)(Sc + (RWQ * w + r) * SP + j4);
                #pragma unroll
                for (int jj = 0; jj < 4; ++jj) {
                    unsigned long long v2 = *(const unsigned long long*)(
                        vcol + (size_t)(KB + j4 + jj) * D);
                    #pragma unroll
                    for (int r = 0; r < RWQ; ++r) {
                        float pp = jj == 0 ? p4[r].x : jj == 1 ? p4[r].y
                                 : jj == 2 ? p4[r].z : p4[r].w;
                        a[r] = ffma2(a[r], dup2(pp), v2);
                    }
                }
            }
        } else {
            #pragma unroll 2
            for (int j4 = 0; j4 < KR; j4 += 4) {
                float4 p4[RWQ];
                #pragma unroll
                for (int r = 0; r < RWQ; ++r)
                    p4[r] = *(const float4*)(Sc + (RWQ * w + r) * SP + j4);
                #pragma unroll
                for (int jj = 0; jj < 4; ++jj) {
                    int kg = min(max(KB + j4 + jj, 0), S - 1);  // p==0 outside
                    unsigned long long v2 = *(const unsigned long long*)(
                        vcol + (size_t)kg * D);
                    #pragma unroll
                    for (int r = 0; r < RWQ; ++r) {
                        float pp = jj == 0 ? p4[r].x : jj == 1 ? p4[r].y
                                 : jj == 2 ? p4[r].z : p4[r].w;
                        a[r] = ffma2(a[r], dup2(pp), v2);
                    }
                }
            }
        }
        #pragma unroll
        for (int r = 0; r < RWQ; ++r) {
            int qq = RWQ * w + r;
            float2 o2 = unpack2(a[r]);
            *(float2*)(O + ((size_t)b * S + qt + qq) * D + 2 * lane) = o2;
        }
    }
}

extern "C" void kernel_launch(void* const* d_in, const int* in_sizes, int n_in,
                              void* d_out, int out_size) {
    const float* q = (const float*)d_in[0];
    const float* k = (const float*)d_in[1];
    const float* v = (const float*)d_in[2];
    float* o = (float*)d_out;
    (void)n_in; (void)out_size;

    cudaFuncSetAttribute(swa_kernel,
                         cudaFuncAttributeMaxDynamicSharedMemorySize, SMEM_BYTES);
    const int B = in_sizes[0] / (S * D);
    swa_kernel<<<B * (S / TQ), NT, SMEM_BYTES>>>(q, k, v, o);
}

// round 6
// speedup vs baseline: 1.5231x; 1.5231x over previous
#include <cuda_runtime.h>

namespace {
constexpr int S  = 8192;
constexpr int D  = 64;
constexpr int W  = 64;
constexpr int TQ = 32;            // queries per CTA
constexpr int KR = TQ + 2 * W;    // 160 key rows per CTA
constexpr int SP = 164;           // P row pitch (float4 aligned)
constexpr int NT = 256;           // 8 warps; each owns 4 query rows
constexpr int RWQ = 4;
// Ks (swizzled) [KR][64] + Qs [TQ][64] + Sc [TQ][SP]
constexpr int SMEM_FLOATS = KR * 64 + TQ * 64 + TQ * SP;
constexpr int SMEM_BYTES  = SMEM_FLOATS * 4;   // 70144 B -> 3 CTAs/SM (210KB<=228KB)
}

// ---- packed f32x2 helpers --------------------------------------------------
__device__ __forceinline__ unsigned long long ffma2(unsigned long long acc,
                                                    unsigned long long a,
                                                    unsigned long long b) {
    asm("fma.rn.f32x2 %0, %1, %2, %0;" : "+l"(acc) : "l"(a), "l"(b));
    return acc;
}
__device__ __forceinline__ unsigned long long dup2(float p) {
    unsigned long long u;
    asm("mov.b64 %0, {%1, %1};" : "=l"(u) : "f"(p));
    return u;
}
__device__ __forceinline__ float2 unpack2(unsigned long long u) {
    float2 v;
    asm("mov.b64 {%0, %1}, %2;" : "=f"(v.x), "=f"(v.y) : "l"(u));
    return v;
}

__global__ __launch_bounds__(NT, 3)
void swa_kernel(const float* __restrict__ Q,
                const float* __restrict__ K,
                const float* __restrict__ V,
                float* __restrict__ O) {
    extern __shared__ float sm[];
    float* Ks = sm;                 // KR x 64, float2-XOR-swizzled within row
    float* Qs = Ks + KR * 64;       // TQ x 64
    float* Sc = Qs + TQ * 64;       // TQ x SP  (normalized P, per-warp private)

    const int tile = blockIdx.x;
    const int b  = tile >> 8;
    const int qt = (tile & 255) * TQ;
    const int KB = qt - W;

    const float* kb = K + (size_t)b * S * D;
    const float* vb = V + (size_t)b * S * D;
    const float* qb = Q + (size_t)b * S * D;

    const int t = threadIdx.x;

    // ---------------- stage K (swizzled) and Q ----------------------------
    for (int idx = t; idx < KR * (D / 4); idx += NT) {
        int row = idx >> 4, c0 = idx & 15;
        int kg = KB + row;
        float4 k4 = make_float4(0.f, 0.f, 0.f, 0.f);
        if (kg >= 0 && kg < S)
            k4 = *(const float4*)(kb + (size_t)kg * D + 4 * c0);
        int x = row & 31;                       // pair (row,d2) -> 2*(d2^x)
        float* krow = Ks + row * 64;
        *(float2*)(krow + 2 * ((2 * c0)     ^ x)) = make_float2(k4.x, k4.y);
        *(float2*)(krow + 2 * ((2 * c0 + 1) ^ x)) = make_float2(k4.z, k4.w);
    }
    for (int idx = t; idx < TQ * (D / 4); idx += NT) {
        int row = idx >> 4, c = (idx & 15) << 2;
        *(float4*)(Qs + row * 64 + c) =
            *(const float4*)(qb + (size_t)(qt + row) * D + c);
    }
    __syncthreads();

    const int lane = t & 31;
    const int w    = t >> 5;   // warp w: rows [4w, 4w+4)

    float p[RWQ][5];           // scores -> normalized probs, register resident

    // ---------------- score GEMM (single pass, immediate K offsets) -------
    {
        unsigned long long acc[RWQ][5];
        #pragma unroll
        for (int r = 0; r < RWQ; ++r)
            #pragma unroll
            for (int s = 0; s < 5; ++s) acc[r][s] = 0ull;

        // single base pointer; key column s at compile-time offset s*2048 floats
        const float* kbase = Ks + lane * 64;
        const float* qrow  = Qs + (RWQ * w) * 64;

        #pragma unroll 2
        for (int d4 = 0; d4 < 16; ++d4) {
            ulonglong2 q2[RWQ];
            #pragma unroll
            for (int r = 0; r < RWQ; ++r)       // LDS.128 broadcast
                q2[r] = *(const ulonglong2*)(qrow + r * 64 + 4 * d4);
            #pragma unroll
            for (int h = 0; h < 2; ++h) {
                const float* kp = kbase + 2 * ((2 * d4 + h) ^ lane);
                unsigned long long kk[5];
                #pragma unroll
                for (int s = 0; s < 5; ++s)     // LDS.64 CF, imm offset s*8192B
                    kk[s] = *(const unsigned long long*)(kp + s * 2048);
                #pragma unroll
                for (int r = 0; r < RWQ; ++r) {
                    unsigned long long qq = h ? q2[r].y : q2[r].x;
                    #pragma unroll
                    for (int s = 0; s < 5; ++s)
                        acc[r][s] = ffma2(acc[r][s], qq, kk[s]);
                }
            }
        }
        #pragma unroll
        for (int r = 0; r < RWQ; ++r)
            #pragma unroll
            for (int s = 0; s < 5; ++s) {
                float2 v = unpack2(acc[r][s]);
                p[r][s] = (v.x + v.y) * 0.125f;
            }
    }

    // ---------------- in-register masked softmax (per warp-owned rows) ----
    #pragma unroll
    for (int r = 0; r < RWQ; ++r) {
        const int row = RWQ * w + r;
        const int lo = max(row, -KB);
        const int hi = min(row + 2 * W, S - 1 - KB);
        float m = -1e30f;
        #pragma unroll
        for (int s = 0; s < 5; ++s) {
            int j = lane + 32 * s;
            if (j >= lo && j <= hi) m = fmaxf(m, p[r][s]);
        }
        m = fmaxf(m, __shfl_xor_sync(0xffffffffu, m, 16));
        m = fmaxf(m, __shfl_xor_sync(0xffffffffu, m, 8));
        m = fmaxf(m, __shfl_xor_sync(0xffffffffu, m, 4));
        m = fmaxf(m, __shfl_xor_sync(0xffffffffu, m, 2));
        m = fmaxf(m, __shfl_xor_sync(0xffffffffu, m, 1));
        float ssum = 0.f;
        #pragma unroll
        for (int s = 0; s < 5; ++s) {
            int j = lane + 32 * s;
            float e = (j >= lo && j <= hi) ? __expf(p[r][s] - m) : 0.f;
            ssum += e;
            p[r][s] = e;
        }
        ssum += __shfl_xor_sync(0xffffffffu, ssum, 16);
        ssum += __shfl_xor_sync(0xffffffffu, ssum, 8);
        ssum += __shfl_xor_sync(0xffffffffu, ssum, 4);
        ssum += __shfl_xor_sync(0xffffffffu, ssum, 2);
        ssum += __shfl_xor_sync(0xffffffffu, ssum, 1);
        float rinv = 1.f / ssum;
        #pragma unroll
        for (int s = 0; s < 5; ++s)             // conflict-free scalar STS
            Sc[row * SP + lane + 32 * s] = p[r][s] * rinv;
    }
    __syncwarp();   // intra-warp transpose only: Sc rows [4w,4w+4) are private

    // ---------------- AV: V straight from gmem (coalesced, L1-reused) -----
    {
        unsigned long long a[RWQ] = {0ull, 0ull, 0ull, 0ull};
        const bool interior = (KB >= 0) && (KB + KR <= S);
        const float* vcol = vb + 2 * lane;

        if (interior) {
            #pragma unroll 2
            for (int j4 = 0; j4 < KR; j4 += 4) {
                float4 p4[RWQ];
                #pragma unroll
                for (int r = 0; r < RWQ; ++r)   // LDS.128 broadcast
                    p4[r] = *(const float4*)(Sc + (RWQ * w + r) * SP + j4);
                #pragma unroll
                for (int jj = 0; jj < 4; ++jj) {
                    unsigned long long v2 = *(const unsigned long long*)(
                        vcol + (size_t)(KB + j4 + jj) * D);
                    #pragma unroll
                    for (int r = 0; r < RWQ; ++r) {
                        float pp = jj == 0 ? p4[r].x : jj == 1 ? p4[r].y
                                 : jj == 2 ? p4[r].z : p4[r].w;
                        a[r] = ffma2(a[r], dup2(pp), v2);
                    }
                }
            }
        } else {
            #pragma unroll 2
            for (int j4 = 0; j4 < KR; j4 += 4) {
                float4 p4[RWQ];
                #pragma unroll
                for (int r = 0; r < RWQ; ++r)
                    p4[r] = *(const float4*)(Sc + (RWQ * w + r) * SP + j4);
                #pragma unroll
                for (int jj = 0; jj < 4; ++jj) {
                    int kg = min(max(KB + j4 + jj, 0), S - 1);  // p==0 outside
                    unsigned long long v2 = *(const unsigned long long*)(
                        vcol + (size_t)kg * D);
                    #pragma unroll
                    for (int r = 0; r < RWQ; ++r) {
                        float pp = jj == 0 ? p4[r].x : jj == 1 ? p4[r].y
                                 : jj == 2 ? p4[r].z : p4[r].w;
                        a[r] = ffma2(a[r], dup2(pp), v2);
                    }
                }
            }
        }
        #pragma unroll
        for (int r = 0; r < RWQ; ++r) {
            int qq = RWQ * w + r;
            float2 o2 = unpack2(a[r]);
            *(float2*)(O + ((size_t)b * S + qt + qq) * D + 2 * lane) = o2;
        }
    }
}

extern "C" void kernel_launch(void* const* d_in, const int* in_sizes, int n_in,
                              void* d_out, int out_size) {
    const float* q = (const float*)d_in[0];
    const float* k = (const float*)d_in[1];
    const float* v = (const float*)d_in[2];
    float* o = (float*)d_out;
    (void)n_in; (void)out_size;

    cudaFuncSetAttribute(swa_kernel,
                         cudaFuncAttributeMaxDynamicSharedMemorySize, SMEM_BYTES);
    const int B = in_sizes[0] / (S * D);
    swa_kernel<<<B * (S / TQ), NT, SMEM_BYTES>>>(q, k, v, o);
}

// round 9
// speedup vs baseline: 2.1556x; 1.4153x over previous
#include <cuda_runtime.h>
#include <cuda_bf16.h>
#include <cstdint>

namespace {
constexpr int S  = 8192;
constexpr int D  = 64;
constexpr int TQ = 128;            // queries per CTA
constexpr int KR = 256;            // key rows per CTA
constexpr int NT = 256;            // 8 warps x 16 query rows

// smem tiles: bf16 [rows][64], 128 B/row, swizzled (c16 ^= row&7)
constexpr int SM_QH = 0;           // 128*128 = 16384
constexpr int SM_QL = 16384;
constexpr int SM_KH = 32768;       // 256*128 = 32768
constexpr int SM_KL = 65536;
constexpr int SM_VH = 98304;
constexpr int SM_VL = 131072;
constexpr int SMEM_BYTES = 163840; // 160 KB -> 1 CTA/SM
}

__device__ __forceinline__ uint32_t smem_u32(const void* p) {
    uint32_t a;
    asm("{ .reg .u64 t; cvta.to.shared.u64 t, %1; cvt.u32.u64 %0, t; }" : "=r"(a) : "l"(p));
    return a;
}
__device__ __forceinline__ uint32_t tile_addr(uint32_t base, int row, int c16) {
    return base + row * 128 + ((uint32_t)(c16 ^ (row & 7)) << 4);
}
// fp32 pair -> packed bf16 hi pair + bf16 lo (residual) pair
__device__ __forceinline__ void split2(float x0, float x1, uint32_t& hi, uint32_t& lo) {
    __nv_bfloat16 h0 = __float2bfloat16(x0);
    __nv_bfloat16 h1 = __float2bfloat16(x1);
    __nv_bfloat16 l0 = __float2bfloat16(x0 - __bfloat162float(h0));
    __nv_bfloat16 l1 = __float2bfloat16(x1 - __bfloat162float(h1));
    hi = (uint32_t)__bfloat16_as_ushort(h0) | ((uint32_t)__bfloat16_as_ushort(h1) << 16);
    lo = (uint32_t)__bfloat16_as_ushort(l0) | ((uint32_t)__bfloat16_as_ushort(l1) << 16);
}
__device__ __forceinline__ void ldsm4(uint32_t& r0, uint32_t& r1, uint32_t& r2, uint32_t& r3,
                                      uint32_t addr) {
    asm volatile("ldmatrix.sync.aligned.m8n8.x4.shared.b16 {%0,%1,%2,%3}, [%4];"
                 : "=r"(r0), "=r"(r1), "=r"(r2), "=r"(r3) : "r"(addr));
}
__device__ __forceinline__ void ldsm4t(uint32_t& r0, uint32_t& r1, uint32_t& r2, uint32_t& r3,
                                       uint32_t addr) {
    asm volatile("ldmatrix.sync.aligned.m8n8.x4.trans.shared.b16 {%0,%1,%2,%3}, [%4];"
                 : "=r"(r0), "=r"(r1), "=r"(r2), "=r"(r3) : "r"(addr));
}
__device__ __forceinline__ void mma16816(float* d, const uint32_t* a, uint32_t b0, uint32_t b1) {
    asm volatile("mma.sync.aligned.m16n8k16.row.col.f32.bf16.bf16.f32 "
                 "{%0,%1,%2,%3}, {%4,%5,%6,%7}, {%8,%9}, {%0,%1,%2,%3};"
                 : "+f"(d[0]), "+f"(d[1]), "+f"(d[2]), "+f"(d[3])
                 : "r"(a[0]), "r"(a[1]), "r"(a[2]), "r"(a[3]), "r"(b0), "r"(b1));
}

__global__ __launch_bounds__(NT, 1)
void swa_mma_kernel(const float* __restrict__ Q,
                    const float* __restrict__ K,
                    const float* __restrict__ V,
                    float* __restrict__ O) {
    extern __shared__ char smem[];
    const uint32_t sb = smem_u32(smem);
    const int t = threadIdx.x;

    const int tile = blockIdx.x;
    const int b  = tile >> 6;              // 64 tiles per batch
    const int qt = (tile & 63) * TQ;
    const int KB = qt - 64;                // global row of key slot 0

    const float* qb = Q + (size_t)b * S * D;
    const float* kb = K + (size_t)b * S * D;
    const float* vb = V + (size_t)b * S * D;

    // ---------------- stage fp32 -> bf16 hi/lo tiles (swizzled) -----------
    for (int idx = t; idx < TQ * 32; idx += NT) {          // 32 d-pairs per row
        int row = idx >> 5, d2 = idx & 31;
        float2 f = *(const float2*)(qb + (size_t)(qt + row) * D + 2 * d2);
        uint32_t hi, lo;  split2(f.x, f.y, hi, lo);
        uint32_t off = row * 128 + (((uint32_t)((d2 >> 2) ^ (row & 7))) << 4) + (d2 & 3) * 4;
        *(uint32_t*)(smem + SM_QH + off) = hi;
        *(uint32_t*)(smem + SM_QL + off) = lo;
    }
    for (int idx = t; idx < KR * 32; idx += NT) {
        int row = idx >> 5, d2 = idx & 31;
        int kg = KB + row;
        float2 fk = make_float2(0.f, 0.f), fv = make_float2(0.f, 0.f);
        if (kg >= 0 && kg < S) {
            fk = *(const float2*)(kb + (size_t)kg * D + 2 * d2);
            fv = *(const float2*)(vb + (size_t)kg * D + 2 * d2);
        }
        uint32_t off = row * 128 + (((uint32_t)((d2 >> 2) ^ (row & 7))) << 4) + (d2 & 3) * 4;
        uint32_t hi, lo;
        split2(fk.x, fk.y, hi, lo);
        *(uint32_t*)(smem + SM_KH + off) = hi;
        *(uint32_t*)(smem + SM_KL + off) = lo;
        split2(fv.x, fv.y, hi, lo);
        *(uint32_t*)(smem + SM_VH + off) = hi;
        *(uint32_t*)(smem + SM_VL + off) = lo;
    }
    __syncthreads();

    const int lane = t & 31;
    const int w    = t >> 5;
    const int r    = lane >> 2;            // 0..7
    const int c    = lane & 3;             // 0..3
    const int rl0  = w * 16 + r;           // local query rows owned by this lane
    const int rl1  = rl0 + 8;
    const int mat  = lane >> 3;            // ldmatrix sub-matrix index
    const int lrow = lane & 7;             // row within sub-matrix

    // band limits in local key coords
    const int lo0 = max(rl0, -KB), hi0 = min(rl0 + 128, S - 1 - KB);
    const int lo1 = max(rl1, -KB), hi1 = min(rl1 + 128, S - 1 - KB);

    // ---------------- Q A-fragments (persist across chunks) ---------------
    uint32_t qh[4][4], ql[4][4];
    {
        int qrow = w * 16 + (mat & 1) * 8 + lrow;
        #pragma unroll
        for (int ks = 0; ks < 4; ++ks) {
            int c16 = ks * 2 + (mat >> 1);
            ldsm4(qh[ks][0], qh[ks][1], qh[ks][2], qh[ks][3],
                  tile_addr(sb + SM_QH, qrow, c16));
            ldsm4(ql[ks][0], ql[ks][1], ql[ks][2], ql[ks][3],
                  tile_addr(sb + SM_QL, qrow, c16));
        }
    }

    float oacc[8][4];
    #pragma unroll
    for (int j = 0; j < 8; ++j)
        #pragma unroll
        for (int e = 0; e < 4; ++e) oacc[j][e] = 0.f;
    float sig0 = 0.f, sig1 = 0.f;

    #pragma unroll
    for (int ch = 0; ch < 4; ++ch) {
        const int kbase = ch * 64;

        // ---- scores: S = Qh*Kh + Ql*Kh + Qh*Kl  (16 x 64 per warp) -------
        float sacc[8][4];
        #pragma unroll
        for (int j = 0; j < 8; ++j)
            #pragma unroll
            for (int e = 0; e < 4; ++e) sacc[j][e] = 0.f;

        #pragma unroll
        for (int ks = 0; ks < 4; ++ks) {
            #pragma unroll
            for (int g = 0; g < 4; ++g) {
                int krow = kbase + g * 16 + ((mat >> 1) & 1) * 8 + lrow;
                int c16  = ks * 2 + (mat & 1);
                uint32_t b0, b1, b2, b3;
                ldsm4(b0, b1, b2, b3, tile_addr(sb + SM_KH, krow, c16));
                mma16816(sacc[2 * g],     qh[ks], b0, b1);
                mma16816(sacc[2 * g + 1], qh[ks], b2, b3);
                mma16816(sacc[2 * g],     ql[ks], b0, b1);
                mma16816(sacc[2 * g + 1], ql[ks], b2, b3);
                ldsm4(b0, b1, b2, b3, tile_addr(sb + SM_KL, krow, c16));
                mma16816(sacc[2 * g],     qh[ks], b0, b1);
                mma16816(sacc[2 * g + 1], qh[ks], b2, b3);
            }
        }

        // ---- masked exp (no max-sub), sigma accumulation ------------------
        #pragma unroll
        for (int j = 0; j < 8; ++j) {
            int col0 = kbase + 8 * j + 2 * c;
            int col1 = col0 + 1;
            float e0 = (col0 >= lo0 && col0 <= hi0) ? __expf(sacc[j][0] * 0.125f) : 0.f;
            float e1 = (col1 >= lo0 && col1 <= hi0) ? __expf(sacc[j][1] * 0.125f) : 0.f;
            float e2 = (col0 >= lo1 && col0 <= hi1) ? __expf(sacc[j][2] * 0.125f) : 0.f;
            float e3 = (col1 >= lo1 && col1 <= hi1) ? __expf(sacc[j][3] * 0.125f) : 0.f;
            sig0 += e0 + e1;
            sig1 += e2 + e3;
            sacc[j][0] = e0; sacc[j][1] = e1; sacc[j][2] = e2; sacc[j][3] = e3;
        }

        // ---- PV: O += Ph*Vh + Pl*Vh + Ph*Vl  (P frags from registers) ----
        #pragma unroll
        for (int kk = 0; kk < 4; ++kk) {
            uint32_t ah[4], al[4];
            split2(sacc[2 * kk][0],     sacc[2 * kk][1],     ah[0], al[0]);
            split2(sacc[2 * kk][2],     sacc[2 * kk][3],     ah[1], al[1]);
            split2(sacc[2 * kk + 1][0], sacc[2 * kk + 1][1], ah[2], al[2]);
            split2(sacc[2 * kk + 1][2], sacc[2 * kk + 1][3], ah[3], al[3]);
            int vrow = kbase + kk * 16 + (mat & 1) * 8 + lrow;
            #pragma unroll
            for (int g = 0; g < 4; ++g) {
                int c16 = g * 2 + (mat >> 1);
                uint32_t v0, v1, v2, v3;
                ldsm4t(v0, v1, v2, v3, tile_addr(sb + SM_VH, vrow, c16));
                mma16816(oacc[2 * g],     ah, v0, v1);
                mma16816(oacc[2 * g + 1], ah, v2, v3);
                mma16816(oacc[2 * g],     al, v0, v1);
                mma16816(oacc[2 * g + 1], al, v2, v3);
                ldsm4t(v0, v1, v2, v3, tile_addr(sb + SM_VL, vrow, c16));
                mma16816(oacc[2 * g],     ah, v0, v1);
                mma16816(oacc[2 * g + 1], ah, v2, v3);
            }
        }
    }

    // ---------------- normalize + write -----------------------------------
    sig0 += __shfl_xor_sync(0xffffffffu, sig0, 1);
    sig0 += __shfl_xor_sync(0xffffffffu, sig0, 2);
    sig1 += __shfl_xor_sync(0xffffffffu, sig1, 1);
    sig1 += __shfl_xor_sync(0xffffffffu, sig1, 2);
    float rinv0 = 1.f / sig0;
    float rinv1 = 1.f / sig1;

    float* o0 = O + ((size_t)b * S + qt + rl0) * D;
    float* o1 = O + ((size_t)b * S + qt + rl1) * D;
    #pragma unroll
    for (int j = 0; j < 8; ++j) {
        *(float2*)(o0 + 8 * j + 2 * c) = make_float2(oacc[j][0] * rinv0, oacc[j][1] * rinv0);
        *(float2*)(o1 + 8 * j + 2 * c) = make_float2(oacc[j][2] * rinv1, oacc[j][3] * rinv1);
    }
}

extern "C" void kernel_launch(void* const* d_in, const int* in_sizes, int n_in,
                              void* d_out, int out_size) {
    const float* q = (const float*)d_in[0];
    const float* k = (const float*)d_in[1];
    const float* v = (const float*)d_in[2];
    float* o = (float*)d_out;
    (void)n_in; (void)out_size;

    cudaFuncSetAttribute(swa_mma_kernel,
                         cudaFuncAttributeMaxDynamicSharedMemorySize, SMEM_BYTES);
    const int B = in_sizes[0] / (S * D);           // 2
    swa_mma_kernel<<<B * (S / TQ), NT, SMEM_BYTES>>>(q, k, v, o);
}

// round 11
// speedup vs baseline: 2.2045x; 1.0227x over previous
#include <cuda_runtime.h>
#include <cuda_bf16.h>
#include <cstdint>

namespace {
constexpr int S  = 8192;
constexpr int D  = 64;
constexpr int TQ = 64;             // queries per CTA
constexpr int KR = 192;            // key rows per CTA (TQ + 2*64)
constexpr int NT = 128;            // 4 warps x 16 query rows

// smem tiles: bf16 [rows][64], 128 B/row, swizzled (c16 ^= row&7)
constexpr int SM_QH = 0;           // 64*128  = 8192
constexpr int SM_QL = 8192;
constexpr int SM_KH = 16384;       // 192*128 = 24576
constexpr int SM_KL = 40960;
constexpr int SM_VH = 65536;
constexpr int SM_VL = 90112;
constexpr int SMEM_BYTES = 114688; // 112 KB -> 2 CTAs/SM (224 KB <= 228 KB)
}

__device__ __forceinline__ uint32_t smem_u32(const void* p) {
    uint32_t a;
    asm("{ .reg .u64 t; cvta.to.shared.u64 t, %1; cvt.u32.u64 %0, t; }" : "=r"(a) : "l"(p));
    return a;
}
__device__ __forceinline__ uint32_t tile_addr(uint32_t base, int row, int c16) {
    return base + row * 128 + ((uint32_t)(c16 ^ (row & 7)) << 4);
}
// fp32 pair -> packed bf16 hi pair + bf16 lo (residual) pair
__device__ __forceinline__ void split2(float x0, float x1, uint32_t& hi, uint32_t& lo) {
    __nv_bfloat16 h0 = __float2bfloat16(x0);
    __nv_bfloat16 h1 = __float2bfloat16(x1);
    __nv_bfloat16 l0 = __float2bfloat16(x0 - __bfloat162float(h0));
    __nv_bfloat16 l1 = __float2bfloat16(x1 - __bfloat162float(h1));
    hi = (uint32_t)__bfloat16_as_ushort(h0) | ((uint32_t)__bfloat16_as_ushort(h1) << 16);
    lo = (uint32_t)__bfloat16_as_ushort(l0) | ((uint32_t)__bfloat16_as_ushort(l1) << 16);
}
__device__ __forceinline__ void ldsm4(uint32_t& r0, uint32_t& r1, uint32_t& r2, uint32_t& r3,
                                      uint32_t addr) {
    asm volatile("ldmatrix.sync.aligned.m8n8.x4.shared.b16 {%0,%1,%2,%3}, [%4];"
                 : "=r"(r0), "=r"(r1), "=r"(r2), "=r"(r3) : "r"(addr));
}
__device__ __forceinline__ void ldsm4t(uint32_t& r0, uint32_t& r1, uint32_t& r2, uint32_t& r3,
                                       uint32_t addr) {
    asm volatile("ldmatrix.sync.aligned.m8n8.x4.trans.shared.b16 {%0,%1,%2,%3}, [%4];"
                 : "=r"(r0), "=r"(r1), "=r"(r2), "=r"(r3) : "r"(addr));
}
__device__ __forceinline__ void mma16816(float* d, const uint32_t* a, uint32_t b0, uint32_t b1) {
    asm volatile("mma.sync.aligned.m16n8k16.row.col.f32.bf16.bf16.f32 "
                 "{%0,%1,%2,%3}, {%4,%5,%6,%7}, {%8,%9}, {%0,%1,%2,%3};"
                 : "+f"(d[0]), "+f"(d[1]), "+f"(d[2]), "+f"(d[3])
                 : "r"(a[0]), "r"(a[1]), "r"(a[2]), "r"(a[3]), "r"(b0), "r"(b1));
}

__global__ __launch_bounds__(NT, 2)
void swa_mma_kernel(const float* __restrict__ Q,
                    const float* __restrict__ K,
                    const float* __restrict__ V,
                    float* __restrict__ O) {
    extern __shared__ char smem[];
    const uint32_t sb = smem_u32(smem);
    const int t = threadIdx.x;

    const int tile = blockIdx.x;
    const int b  = tile >> 7;              // 128 tiles per batch
    const int qt = (tile & 127) * TQ;
    const int KB = qt - 64;                // global row of key slot 0

    const float* qb = Q + (size_t)b * S * D;
    const float* kb = K + (size_t)b * S * D;
    const float* vb = V + (size_t)b * S * D;

    // ---------------- stage fp32 -> bf16 hi/lo tiles (swizzled) -----------
    for (int idx = t; idx < TQ * 32; idx += NT) {          // 32 d-pairs per row
        int row = idx >> 5, d2 = idx & 31;
        float2 f = *(const float2*)(qb + (size_t)(qt + row) * D + 2 * d2);
        uint32_t hi, lo;  split2(f.x, f.y, hi, lo);
        uint32_t off = row * 128 + (((uint32_t)((d2 >> 2) ^ (row & 7))) << 4) + (d2 & 3) * 4;
        *(uint32_t*)(smem + SM_QH + off) = hi;
        *(uint32_t*)(smem + SM_QL + off) = lo;
    }
    for (int idx = t; idx < KR * 32; idx += NT) {
        int row = idx >> 5, d2 = idx & 31;
        int kg = KB + row;
        float2 fk = make_float2(0.f, 0.f), fv = make_float2(0.f, 0.f);
        if (kg >= 0 && kg < S) {
            fk = *(const float2*)(kb + (size_t)kg * D + 2 * d2);
            fv = *(const float2*)(vb + (size_t)kg * D + 2 * d2);
        }
        uint32_t off = row * 128 + (((uint32_t)((d2 >> 2) ^ (row & 7))) << 4) + (d2 & 3) * 4;
        uint32_t hi, lo;
        split2(fk.x, fk.y, hi, lo);
        *(uint32_t*)(smem + SM_KH + off) = hi;
        *(uint32_t*)(smem + SM_KL + off) = lo;
        split2(fv.x, fv.y, hi, lo);
        *(uint32_t*)(smem + SM_VH + off) = hi;
        *(uint32_t*)(smem + SM_VL + off) = lo;
    }
    __syncthreads();

    const int lane = t & 31;
    const int w    = t >> 5;               // 0..3
    const int r    = lane >> 2;            // 0..7
    const int c    = lane & 3;             // 0..3
    const int rl0  = w * 16 + r;           // local query rows owned by this lane
    const int rl1  = rl0 + 8;
    const int mat  = lane >> 3;            // ldmatrix sub-matrix index
    const int lrow = lane & 7;             // row within sub-matrix

    // band limits in local key coords
    const int lo0 = max(rl0, -KB), hi0 = min(rl0 + 128, S - 1 - KB);
    const int lo1 = max(rl1, -KB), hi1 = min(rl1 + 128, S - 1 - KB);

    // ---------------- Q A-fragments (persist across chunks) ---------------
    uint32_t qh[4][4], ql[4][4];
    {
        int qrow = w * 16 + (mat & 1) * 8 + lrow;
        #pragma unroll
        for (int ks = 0; ks < 4; ++ks) {
            int c16 = ks * 2 + (mat >> 1);
            ldsm4(qh[ks][0], qh[ks][1], qh[ks][2], qh[ks][3],
                  tile_addr(sb + SM_QH, qrow, c16));
            ldsm4(ql[ks][0], ql[ks][1], ql[ks][2], ql[ks][3],
                  tile_addr(sb + SM_QL, qrow, c16));
        }
    }

    float oacc[8][4];
    #pragma unroll
    for (int j = 0; j < 8; ++j)
        #pragma unroll
        for (int e = 0; e < 4; ++e) oacc[j][e] = 0.f;
    float sig0 = 0.f, sig1 = 0.f;

    #pragma unroll
    for (int ch = 0; ch < 3; ++ch) {
        const int kbase = ch * 64;

        // ---- scores: S = Qh*Kh + Ql*Kh + Qh*Kl  (16 x 64 per warp) -------
        float sacc[8][4];
        #pragma unroll
        for (int j = 0; j < 8; ++j)
            #pragma unroll
            for (int e = 0; e < 4; ++e) sacc[j][e] = 0.f;

        #pragma unroll
        for (int ks = 0; ks < 4; ++ks) {
            #pragma unroll
            for (int g = 0; g < 4; ++g) {
                int krow = kbase + g * 16 + ((mat >> 1) & 1) * 8 + lrow;
                int c16  = ks * 2 + (mat & 1);
                uint32_t b0, b1, b2, b3;
                ldsm4(b0, b1, b2, b3, tile_addr(sb + SM_KH, krow, c16));
                mma16816(sacc[2 * g],     qh[ks], b0, b1);
                mma16816(sacc[2 * g + 1], qh[ks], b2, b3);
                mma16816(sacc[2 * g],     ql[ks], b0, b1);
                mma16816(sacc[2 * g + 1], ql[ks], b2, b3);
                ldsm4(b0, b1, b2, b3, tile_addr(sb + SM_KL, krow, c16));
                mma16816(sacc[2 * g],     qh[ks], b0, b1);
                mma16816(sacc[2 * g + 1], qh[ks], b2, b3);
            }
        }

        // ---- masked exp (no max-sub), sigma accumulation ------------------
        #pragma unroll
        for (int j = 0; j < 8; ++j) {
            int col0 = kbase + 8 * j + 2 * c;
            int col1 = col0 + 1;
            float e0 = (col0 >= lo0 && col0 <= hi0) ? __expf(sacc[j][0] * 0.125f) : 0.f;
            float e1 = (col1 >= lo0 && col1 <= hi0) ? __expf(sacc[j][1] * 0.125f) : 0.f;
            float e2 = (col0 >= lo1 && col0 <= hi1) ? __expf(sacc[j][2] * 0.125f) : 0.f;
            float e3 = (col1 >= lo1 && col1 <= hi1) ? __expf(sacc[j][3] * 0.125f) : 0.f;
            sig0 += e0 + e1;
            sig1 += e2 + e3;
            sacc[j][0] = e0; sacc[j][1] = e1; sacc[j][2] = e2; sacc[j][3] = e3;
        }

        // ---- PV: O += Ph*Vh + Pl*Vh + Ph*Vl  (P frags from registers) ----
        #pragma unroll
        for (int kk = 0; kk < 4; ++kk) {
            uint32_t ah[4], al[4];
            split2(sacc[2 * kk][0],     sacc[2 * kk][1],     ah[0], al[0]);
            split2(sacc[2 * kk][2],     sacc[2 * kk][3],     ah[1], al[1]);
            split2(sacc[2 * kk + 1][0], sacc[2 * kk + 1][1], ah[2], al[2]);
            split2(sacc[2 * kk + 1][2], sacc[2 * kk + 1][3], ah[3], al[3]);
            int vrow = kbase + kk * 16 + (mat & 1) * 8 + lrow;
            #pragma unroll
            for (int g = 0; g < 4; ++g) {
                int c16 = g * 2 + (mat >> 1);
                uint32_t v0, v1, v2, v3;
                ldsm4t(v0, v1, v2, v3, tile_addr(sb + SM_VH, vrow, c16));
                mma16816(oacc[2 * g],     ah, v0, v1);
                mma16816(oacc[2 * g + 1], ah, v2, v3);
                mma16816(oacc[2 * g],     al, v0, v1);
                mma16816(oacc[2 * g + 1], al, v2, v3);
                ldsm4t(v0, v1, v2, v3, tile_addr(sb + SM_VL, vrow, c16));
                mma16816(oacc[2 * g],     ah, v0, v1);
                mma16816(oacc[2 * g + 1], ah, v2, v3);
            }
        }
    }

    // ---------------- normalize + write -----------------------------------
    sig0 += __shfl_xor_sync(0xffffffffu, sig0, 1);
    sig0 += __shfl_xor_sync(0xffffffffu, sig0, 2);
    sig1 += __shfl_xor_sync(0xffffffffu, sig1, 1);
    sig1 += __shfl_xor_sync(0xffffffffu, sig1, 2);
    float rinv0 = 1.f / sig0;
    float rinv1 = 1.f / sig1;

    float* o0 = O + ((size_t)b * S + qt + rl0) * D;
    float* o1 = O + ((size_t)b * S + qt + rl1) * D;
    #pragma unroll
    for (int j = 0; j < 8; ++j) {
        *(float2*)(o0 + 8 * j + 2 * c) = make_float2(oacc[j][0] * rinv0, oacc[j][1] * rinv0);
        *(float2*)(o1 + 8 * j + 2 * c) = make_float2(oacc[j][2] * rinv1, oacc[j][3] * rinv1);
    }
}

extern "C" void kernel_launch(void* const* d_in, const int* in_sizes, int n_in,
                              void* d_out, int out_size) {
    const float* q = (const float*)d_in[0];
    const float* k = (const float*)d_in[1];
    const float* v = (const float*)d_in[2];
    float* o = (float*)d_out;
    (void)n_in; (void)out_size;

    cudaFuncSetAttribute(swa_mma_kernel,
                         cudaFuncAttributeMaxDynamicSharedMemorySize, SMEM_BYTES);
    const int B = in_sizes[0] / (S * D);           // 2
    swa_mma_kernel<<<B * (S / TQ), NT, SMEM_BYTES>>>(q, k, v, o);
}